// round 7
// baseline (speedup 1.0000x reference)
#include <cuda_runtime.h>
#include <cstdint>

// FullTensorProduct, N=4096 rows, MUL=64.
// Per row: a0=in1[:64], a1=in1[64:256] as (64,3); b0,b1 from in2.
// out row (45056 floats):
//   [0,4096)      c000[u*64+v]        = a0[u]*b0[v]
//   [4096,8192)   c110[u*64+v]        = dot(a1[u],b1[v]) / sqrt(3)
//   [8192,20480)  c011[(u*64+v)*3+j]  = a0[u]*b1[v][j]
//   [20480,32768) c101[(u*64+v)*3+i]  = a1[u][i]*b0[v]
//   [32768,45056) c111[(u*64+v)*3+k]  = cross(a1[u],b1[v])[k] / sqrt(2)
//
// R7 = R6 chunk pipeline (2x45KB double buffer, 1 commit/chunk, evict_first)
// made persistent with CHUNK-granular contiguous work ranges:
//   total 16384 chunks / 296 CTAs -> tail imbalance 1 chunk (~2us) instead of
//   R5's 1 row (~8us). Next row's inputs prefetched into regs a row ahead.

constexpr int ROW_IN  = 256;
constexpr int ROW_OUT = 45056;
constexpr int CHUNK_FLOATS = 11264;              // 16 u's = 45056 B
constexpr float INV_SQRT3 = 0.57735026918962576451f;
constexpr float INV_SQRT2 = 0.70710678118654752440f;

__device__ __forceinline__ uint32_t smem_u32(const void* p) {
    uint32_t r;
    asm("{ .reg .u64 t; cvta.to.shared.u64 t, %1; cvt.u32.u64 %0, t; }"
        : "=r"(r) : "l"(p));
    return r;
}

__device__ __forceinline__ uint64_t evict_first_policy() {
    uint64_t pol;
    asm("createpolicy.fractional.L2::evict_first.b64 %0, 1.0;" : "=l"(pol));
    return pol;
}

__device__ __forceinline__ void bulk_store(void* gptr, uint32_t saddr,
                                           uint32_t bytes, uint64_t pol) {
    asm volatile(
        "cp.async.bulk.global.shared::cta.bulk_group.L2::cache_hint "
        "[%0], [%1], %2, %3;"
        :: "l"(gptr), "r"(saddr), "r"(bytes), "l"(pol) : "memory");
}

__global__ __launch_bounds__(256, 2)
void ftp_kernel(const float* __restrict__ in1,
                const float* __restrict__ in2,
                float* __restrict__ out,
                int total_chunks)
{
    __shared__ __align__(16) float a0[64], b0[64];
    __shared__ __align__(16) float a1x[64], a1y[64], a1z[64];
    __shared__ __align__(16) float b1x[64], b1y[64], b1z[64];
    extern __shared__ __align__(16) float buf[];  // 2 * CHUNK_FLOATS

    const int t = threadIdx.x;

    // Contiguous chunk range for this CTA (even split, remainder spread).
    const int start = (int)(((long long)blockIdx.x * total_chunks) / gridDim.x);
    const int end   = (int)(((long long)(blockIdx.x + 1) * total_chunks) / gridDim.x);
    if (start >= end) return;

    const int last_row = (end - 1) >> 2;

    // Prefetch first row's inputs into registers.
    int pref_row = start >> 2;
    float v1 = in1[(size_t)pref_row * ROW_IN + t];
    float v2 = in2[(size_t)pref_row * ROW_IN + t];

    int cur_row = -1;
    float4 b, bx, by, bz;
    float* orow = nullptr;

    for (int ci = start; ci < end; ++ci) {
        const int row = ci >> 2;
        const int k   = ci & 3;
        const int li  = ci - start;

        if (row != cur_row) {
            // Stage this row's inputs (regs -> smem planes). Safe: all compute
            // reads of the previous row finished before the last post-compute
            // __syncthreads (t0's in-flight bulk stores read buf, not these).
            if (t < 64) {
                a0[t] = v1; b0[t] = v2;
            } else {
                int idx = t - 64;
                int u = idx / 3;
                int c3 = idx - 3 * u;
                if (c3 == 0)      { a1x[u] = v1; b1x[u] = v2; }
                else if (c3 == 1) { a1y[u] = v1; b1y[u] = v2; }
                else              { a1z[u] = v1; b1z[u] = v2; }
            }
            __syncthreads();
            cur_row = row;
            orow = out + (size_t)row * ROW_OUT;

            // Per-thread b-side quads for this row.
            const int s = t & 15;
            b  = ((const float4*)b0)[s];
            bx = ((const float4*)b1x)[s];
            by = ((const float4*)b1y)[s];
            bz = ((const float4*)b1z)[s];

            // Prefetch next row (latency hidden behind ~4 chunks of compute).
            if (row < last_row) {
                v1 = in1[(size_t)(row + 1) * ROW_IN + t];
                v2 = in2[(size_t)(row + 1) * ROW_IN + t];
            }
        }

        float* B = buf + (li & 1) * CHUNK_FLOATS;

        if (li >= 2) {
            // Ring reuse: the group that read this buffer must be done.
            if (t == 0)
                asm volatile("cp.async.bulk.wait_group.read 1;" ::: "memory");
            __syncthreads();
        }

        const int u = (k << 4) + (t >> 4);
        const float a  = a0[u];
        const float ax = a1x[u], ay = a1y[u], az = a1z[u];

        float4* B000 = (float4*)(B);            // 256 float4
        float4* B110 = (float4*)(B + 1024);     // 256 float4
        float4* B011 = (float4*)(B + 2048);     // 768 float4
        float4* B101 = (float4*)(B + 5120);     // 768 float4
        float4* B111 = (float4*)(B + 8192);     // 768 float4

        // c000
        B000[t] = make_float4(a * b.x, a * b.y, a * b.z, a * b.w);

        // c110
        {
            float4 r;
            r.x = (ax * bx.x + ay * by.x + az * bz.x) * INV_SQRT3;
            r.y = (ax * bx.y + ay * by.y + az * bz.y) * INV_SQRT3;
            r.z = (ax * bx.z + ay * by.z + az * bz.z) * INV_SQRT3;
            r.w = (ax * bx.w + ay * by.w + az * bz.w) * INV_SQRT3;
            B110[t] = r;
        }

        // c011: a0[u]*b1[v][j], j fastest
        B011[3*t + 0] = make_float4(a*bx.x, a*by.x, a*bz.x, a*bx.y);
        B011[3*t + 1] = make_float4(a*by.y, a*bz.y, a*bx.z, a*by.z);
        B011[3*t + 2] = make_float4(a*bz.z, a*bx.w, a*by.w, a*bz.w);

        // c101: a1[u][i]*b0[v], i fastest
        B101[3*t + 0] = make_float4(ax*b.x, ay*b.x, az*b.x, ax*b.y);
        B101[3*t + 1] = make_float4(ay*b.y, az*b.y, ax*b.z, ay*b.z);
        B101[3*t + 2] = make_float4(az*b.z, ax*b.w, ay*b.w, az*b.w);

        // c111: cross(a1[u], b1[v]) / sqrt(2), k fastest
        {
            const float cx0 = (ay*bz.x - az*by.x) * INV_SQRT2;
            const float cy0 = (az*bx.x - ax*bz.x) * INV_SQRT2;
            const float cz0 = (ax*by.x - ay*bx.x) * INV_SQRT2;
            const float cx1 = (ay*bz.y - az*by.y) * INV_SQRT2;
            const float cy1 = (az*bx.y - ax*bz.y) * INV_SQRT2;
            const float cz1 = (ax*by.y - ay*bx.y) * INV_SQRT2;
            const float cx2 = (ay*bz.z - az*by.z) * INV_SQRT2;
            const float cy2 = (az*bx.z - ax*bz.z) * INV_SQRT2;
            const float cz2 = (ax*by.z - ay*bx.z) * INV_SQRT2;
            const float cx3 = (ay*bz.w - az*by.w) * INV_SQRT2;
            const float cy3 = (az*bx.w - ax*bz.w) * INV_SQRT2;
            const float cz3 = (ax*by.w - ay*bx.w) * INV_SQRT2;
            B111[3*t + 0] = make_float4(cx0, cy0, cz0, cx1);
            B111[3*t + 1] = make_float4(cy1, cz1, cx2, cy2);
            B111[3*t + 2] = make_float4(cz2, cx3, cy3, cz3);
        }

        __syncthreads();

        if (t == 0) {
            asm volatile("fence.proxy.async.shared::cta;" ::: "memory");
            const uint32_t sb = smem_u32(B);
            const uint64_t pol = evict_first_policy();
            bulk_store(orow +  8192 + 3*(k << 10), sb +  8192, 12288, pol);
            bulk_store(orow + 20480 + 3*(k << 10), sb + 20480, 12288, pol);
            bulk_store(orow + 32768 + 3*(k << 10), sb + 32768, 12288, pol);
            bulk_store(orow +     0 + (k << 10),   sb +     0,  4096, pol);
            bulk_store(orow +  4096 + (k << 10),   sb +  4096,  4096, pol);
            asm volatile("cp.async.bulk.commit_group;" ::: "memory");
        }
    }

    // Drain before exit (smem lifetime / visibility).
    if (t == 0)
        asm volatile("cp.async.bulk.wait_group.read 0;" ::: "memory");
}

extern "C" void kernel_launch(void* const* d_in, const int* in_sizes, int n_in,
                              void* d_out, int out_size)
{
    const float* in1 = (const float*)d_in[0];
    const float* in2 = (const float*)d_in[1];
    float* out = (float*)d_out;
    const int N = in_sizes[0] / ROW_IN;   // 4096 rows
    const int total_chunks = N * 4;

    int dev = 0, nsm = 148;
    cudaGetDevice(&dev);
    cudaDeviceGetAttribute(&nsm, cudaDevAttrMultiProcessorCount, dev);
    int grid = 2 * nsm;
    if (grid > total_chunks) grid = total_chunks;

    const int dyn_smem = 2 * CHUNK_FLOATS * (int)sizeof(float);  // 90112 B
    cudaFuncSetAttribute(ftp_kernel, cudaFuncAttributeMaxDynamicSharedMemorySize, dyn_smem);
    ftp_kernel<<<grid, 256, dyn_smem>>>(in1, in2, out, total_chunks);
}

// round 9
// speedup vs baseline: 1.0791x; 1.0791x over previous
#include <cuda_runtime.h>
#include <cstdint>

// FullTensorProduct, N=4096 rows, MUL=64.
// Per row: a0=in1[:64], a1=in1[64:256] as (64,3); b0,b1 from in2.
// out row (45056 floats):
//   [0,4096)      c000[u*64+v]        = a0[u]*b0[v]
//   [4096,8192)   c110[u*64+v]        = dot(a1[u],b1[v]) / sqrt(3)
//   [8192,20480)  c011[(u*64+v)*3+j]  = a0[u]*b1[v][j]
//   [20480,32768) c101[(u*64+v)*3+i]  = a1[u][i]*b0[v]
//   [32768,45056) c111[(u*64+v)*3+k]  = cross(a1[u],b1[v])[k] / sqrt(2)
//
// R8: output-CONTIGUOUS chunks. Row split into 4 contiguous spans
// (11264 | 12288 | 12288 | 9216 floats), each drained by ONE TMA bulk store:
//   chunk0: c000 full + c110 full + c011 u[0,16)
//   chunk1: c011 u[16,64) + c101 u[0,16)
//   chunk2: c101 u[16,64) + c111 u[0,16)
//   chunk3: c111 u[16,64)
// Each CTA writes its 176KB row strictly front-to-back -> max DRAM page
// locality, 1 TMA request per chunk instead of 5. Double buffer, evict_first,
// grid=4096 (persistent measured slower twice).

constexpr int ROW_IN  = 256;
constexpr int ROW_OUT = 45056;
constexpr int BUF_FLOATS = 12288;                // max chunk (48KB)
constexpr float INV_SQRT3 = 0.57735026918962576451f;
constexpr float INV_SQRT2 = 0.70710678118654752440f;

__device__ __forceinline__ uint32_t smem_u32(const void* p) {
    uint32_t r;
    asm("{ .reg .u64 t; cvta.to.shared.u64 t, %1; cvt.u32.u64 %0, t; }"
        : "=r"(r) : "l"(p));
    return r;
}

__device__ __forceinline__ uint64_t evict_first_policy() {
    uint64_t pol;
    asm("createpolicy.fractional.L2::evict_first.b64 %0, 1.0;" : "=l"(pol));
    return pol;
}

__device__ __forceinline__ void bulk_store(void* gptr, uint32_t saddr,
                                           uint32_t bytes, uint64_t pol) {
    asm volatile(
        "cp.async.bulk.global.shared::cta.bulk_group.L2::cache_hint "
        "[%0], [%1], %2, %3;"
        :: "l"(gptr), "r"(saddr), "r"(bytes), "l"(pol) : "memory");
}

// ---- section emitters ----------------------------------------------------
// Full c000 section (4096 floats): thread t covers u=t>>2, v quads (t&3)*4+j.
__device__ __forceinline__ void emit_full_000(float4* dst, int t,
                                              const float* a0, const float* b0) {
    const float a = a0[t >> 2];
    const int qv = (t & 3) * 4;
    #pragma unroll
    for (int j = 0; j < 4; ++j) {
        const float4 bq = ((const float4*)b0)[qv + j];
        dst[4 * t + j] = make_float4(a * bq.x, a * bq.y, a * bq.z, a * bq.w);
    }
}

// Full c110 section (4096 floats).
__device__ __forceinline__ void emit_full_110(float4* dst, int t,
                                              const float* a1x, const float* a1y, const float* a1z,
                                              const float* b1x, const float* b1y, const float* b1z) {
    const int u = t >> 2;
    const float ax = a1x[u], ay = a1y[u], az = a1z[u];
    const int qv = (t & 3) * 4;
    #pragma unroll
    for (int j = 0; j < 4; ++j) {
        const float4 qx = ((const float4*)b1x)[qv + j];
        const float4 qy = ((const float4*)b1y)[qv + j];
        const float4 qz = ((const float4*)b1z)[qv + j];
        float4 r;
        r.x = (ax * qx.x + ay * qy.x + az * qz.x) * INV_SQRT3;
        r.y = (ax * qx.y + ay * qy.y + az * qz.y) * INV_SQRT3;
        r.z = (ax * qx.z + ay * qy.z + az * qz.z) * INV_SQRT3;
        r.w = (ax * qx.w + ay * qy.w + az * qz.w) * INV_SQRT3;
        dst[4 * t + j] = r;
    }
}

// One 16-u block (3072 floats) of c011: u = 16*blk + (t>>4), pairs 4t..4t+4.
__device__ __forceinline__ void emit_blk_011(float4* dst, int t, int u,
                                             const float* a0,
                                             float4 bx, float4 by, float4 bz) {
    const float a = a0[u];
    dst[3*t + 0] = make_float4(a*bx.x, a*by.x, a*bz.x, a*bx.y);
    dst[3*t + 1] = make_float4(a*by.y, a*bz.y, a*bx.z, a*by.z);
    dst[3*t + 2] = make_float4(a*bz.z, a*bx.w, a*by.w, a*bz.w);
}

__device__ __forceinline__ void emit_blk_101(float4* dst, int t, int u,
                                             const float* a1x, const float* a1y, const float* a1z,
                                             float4 b) {
    const float ax = a1x[u], ay = a1y[u], az = a1z[u];
    dst[3*t + 0] = make_float4(ax*b.x, ay*b.x, az*b.x, ax*b.y);
    dst[3*t + 1] = make_float4(ay*b.y, az*b.y, ax*b.z, ay*b.z);
    dst[3*t + 2] = make_float4(az*b.z, ax*b.w, ay*b.w, az*b.w);
}

__device__ __forceinline__ void emit_blk_111(float4* dst, int t, int u,
                                             const float* a1x, const float* a1y, const float* a1z,
                                             float4 bx, float4 by, float4 bz) {
    const float ax = a1x[u], ay = a1y[u], az = a1z[u];
    const float cx0 = (ay*bz.x - az*by.x) * INV_SQRT2;
    const float cy0 = (az*bx.x - ax*bz.x) * INV_SQRT2;
    const float cz0 = (ax*by.x - ay*bx.x) * INV_SQRT2;
    const float cx1 = (ay*bz.y - az*by.y) * INV_SQRT2;
    const float cy1 = (az*bx.y - ax*bz.y) * INV_SQRT2;
    const float cz1 = (ax*by.y - ay*bx.y) * INV_SQRT2;
    const float cx2 = (ay*bz.z - az*by.z) * INV_SQRT2;
    const float cy2 = (az*bx.z - ax*bz.z) * INV_SQRT2;
    const float cz2 = (ax*by.z - ay*bx.z) * INV_SQRT2;
    const float cx3 = (ay*bz.w - az*by.w) * INV_SQRT2;
    const float cy3 = (az*bx.w - ax*bz.w) * INV_SQRT2;
    const float cz3 = (ax*by.w - ay*bx.w) * INV_SQRT2;
    dst[3*t + 0] = make_float4(cx0, cy0, cz0, cx1);
    dst[3*t + 1] = make_float4(cy1, cz1, cx2, cy2);
    dst[3*t + 2] = make_float4(cz2, cx3, cy3, cz3);
}

__global__ __launch_bounds__(256, 2)
void ftp_kernel(const float* __restrict__ in1,
                const float* __restrict__ in2,
                float* __restrict__ out)
{
    __shared__ __align__(16) float a0[64], b0[64];
    __shared__ __align__(16) float a1x[64], a1y[64], a1z[64];
    __shared__ __align__(16) float b1x[64], b1y[64], b1z[64];
    extern __shared__ __align__(16) float buf[];  // 2 * BUF_FLOATS

    const int row = blockIdx.x;
    const int t   = threadIdx.x;

    // Stage inputs: 256 floats per operand, split a1/b1 into x/y/z planes.
    {
        const float v1 = in1[(size_t)row * ROW_IN + t];
        const float v2 = in2[(size_t)row * ROW_IN + t];
        if (t < 64) {
            a0[t] = v1; b0[t] = v2;
        } else {
            int idx = t - 64;
            int u = idx / 3;
            int c = idx - 3 * u;
            if (c == 0)      { a1x[u] = v1; b1x[u] = v2; }
            else if (c == 1) { a1y[u] = v1; b1y[u] = v2; }
            else             { a1z[u] = v1; b1z[u] = v2; }
        }
    }
    __syncthreads();

    // Per-thread b-side quads for block emitters (s = t&15, fixed all chunks).
    const int s = t & 15;
    const float4 b  = ((const float4*)b0)[s];
    const float4 bx = ((const float4*)b1x)[s];
    const float4 by = ((const float4*)b1y)[s];
    const float4 bz = ((const float4*)b1z)[s];

    float* orow = out + (size_t)row * ROW_OUT;
    const int ulocal = t >> 4;   // 0..15 within a 16-u block

    // Chunk table: global float offset + byte size (contiguous spans).
    const int C_OFF[4]   = {0, 11264, 23552, 35840};
    const int C_BYTES[4] = {45056, 49152, 49152, 36864};

    #pragma unroll
    for (int k = 0; k < 4; ++k) {
        float4* B4 = (float4*)(buf + (k & 1) * BUF_FLOATS);

        if (k >= 2) {
            if (t == 0)
                asm volatile("cp.async.bulk.wait_group.read 1;" ::: "memory");
            __syncthreads();
        }

        if (k == 0) {
            // c000 full | c110 full | c011 blk0
            emit_full_000(B4, t, a0, b0);
            emit_full_110(B4 + 1024, t, a1x, a1y, a1z, b1x, b1y, b1z);
            emit_blk_011(B4 + 2048, t, ulocal, a0, bx, by, bz);
        } else if (k == 1) {
            // c011 blk1,2,3 | c101 blk0
            emit_blk_011(B4 +    0, t, 16 + ulocal, a0, bx, by, bz);
            emit_blk_011(B4 +  768, t, 32 + ulocal, a0, bx, by, bz);
            emit_blk_011(B4 + 1536, t, 48 + ulocal, a0, bx, by, bz);
            emit_blk_101(B4 + 2304, t, ulocal, a1x, a1y, a1z, b);
        } else if (k == 2) {
            // c101 blk1,2,3 | c111 blk0
            emit_blk_101(B4 +    0, t, 16 + ulocal, a1x, a1y, a1z, b);
            emit_blk_101(B4 +  768, t, 32 + ulocal, a1x, a1y, a1z, b);
            emit_blk_101(B4 + 1536, t, 48 + ulocal, a1x, a1y, a1z, b);
            emit_blk_111(B4 + 2304, t, ulocal, a1x, a1y, a1z, bx, by, bz);
        } else {
            // c111 blk1,2,3
            emit_blk_111(B4 +    0, t, 16 + ulocal, a1x, a1y, a1z, bx, by, bz);
            emit_blk_111(B4 +  768, t, 32 + ulocal, a1x, a1y, a1z, bx, by, bz);
            emit_blk_111(B4 + 1536, t, 48 + ulocal, a1x, a1y, a1z, bx, by, bz);
        }

        __syncthreads();

        if (t == 0) {
            asm volatile("fence.proxy.async.shared::cta;" ::: "memory");
            bulk_store(orow + C_OFF[k], smem_u32(B4), C_BYTES[k], evict_first_policy());
            asm volatile("cp.async.bulk.commit_group;" ::: "memory");
        }
    }

    // Drain before exit (smem lifetime / visibility).
    if (t == 0)
        asm volatile("cp.async.bulk.wait_group.read 0;" ::: "memory");
}

extern "C" void kernel_launch(void* const* d_in, const int* in_sizes, int n_in,
                              void* d_out, int out_size)
{
    const float* in1 = (const float*)d_in[0];
    const float* in2 = (const float*)d_in[1];
    float* out = (float*)d_out;
    const int N = in_sizes[0] / ROW_IN;   // 4096 rows

    const int dyn_smem = 2 * BUF_FLOATS * (int)sizeof(float);  // 98304 B
    cudaFuncSetAttribute(ftp_kernel, cudaFuncAttributeMaxDynamicSharedMemorySize, dyn_smem);
    ftp_kernel<<<N, 256, dyn_smem>>>(in1, in2, out);
}